// round 9
// baseline (speedup 1.0000x reference)
#include <cuda_runtime.h>
#include <cuda_bf16.h>
#include <cstdint>

#define NROWS 32768
#define CCLS  2048
#define DDIM  512

// ---- column split: 13 tensor tiles + 3 ffma tiles of 128 ----
#define NTILES    16
#define TENS_TILES 13

// ---- tensor-path tiling (round-7 config: 128x128, 3-stage, 2 CTAs/SM) ----
#define BM 128
#define BN 128
#define BK 64                    // bf16 elems per chunk (128B per row)
#define KCHUNKS 24               // 3 products x (512/64)
#define TILE_BYTES 16384         // 128 rows x 128B
#define STAGE_BYTES (2 * TILE_BYTES)
#define NSTAGES 3
#define SMEM_TOTAL  (NSTAGES * STAGE_BYTES)   // 98304

// ---- ffma-path tiling (round-4 config: 128x128x16, 8x8/thread) ----
#define FBK 16

// ---- scratch (__device__ globals; no cudaMalloc allowed) ----
__device__ __nv_bfloat16 g_Ah[(size_t)NROWS * DDIM];
__device__ __nv_bfloat16 g_Al[(size_t)NROWS * DDIM];
__device__ __nv_bfloat16 g_Bh[(size_t)CCLS * DDIM];
__device__ __nv_bfloat16 g_Bl[(size_t)CCLS * DDIM];
__device__ float g_m2[CCLS];

// ===========================================================================
// PTX helpers (all supported on plain sm_103 target)
// ===========================================================================
__device__ __forceinline__ uint32_t smem_u32(const void* p) {
    uint32_t a;
    asm("{ .reg .u64 t; cvta.to.shared.u64 t, %1; cvt.u32.u64 %0, t; }" : "=r"(a) : "l"(p));
    return a;
}

__device__ __forceinline__ void cp16(uint32_t dst, const void* src) {
    asm volatile("cp.async.cg.shared.global.L2::128B [%0], [%1], 16;" :: "r"(dst), "l"(src));
}
#define CP_COMMIT() asm volatile("cp.async.commit_group;" ::: "memory")
#define CP_WAIT1()  asm volatile("cp.async.wait_group 1;" ::: "memory")

__device__ __forceinline__ void ldsm4(uint32_t* r, uint32_t addr) {
    asm volatile("ldmatrix.sync.aligned.m8n8.x4.shared.b16 {%0,%1,%2,%3}, [%4];"
                 : "=r"(r[0]), "=r"(r[1]), "=r"(r[2]), "=r"(r[3]) : "r"(addr));
}

__device__ __forceinline__ void mma16816(float* d, const uint32_t* a, const uint32_t* b) {
    asm volatile("mma.sync.aligned.m16n8k16.row.col.f32.bf16.bf16.f32 "
                 "{%0,%1,%2,%3}, {%4,%5,%6,%7}, {%8,%9}, {%0,%1,%2,%3};"
                 : "+f"(d[0]), "+f"(d[1]), "+f"(d[2]), "+f"(d[3])
                 : "r"(a[0]), "r"(a[1]), "r"(a[2]), "r"(a[3]), "r"(b[0]), "r"(b[1]));
}

// ===========================================================================
// Kernel: convert X -> bf16 hi/lo
// ===========================================================================
__global__ __launch_bounds__(256) void k_convX(const float* __restrict__ X) {
    const int idx = blockIdx.x * 256 + threadIdx.x;        // float4 index
    float4 v = ((const float4*)X)[idx];
    __nv_bfloat16 h0 = __float2bfloat16(v.x), h1 = __float2bfloat16(v.y);
    __nv_bfloat16 h2 = __float2bfloat16(v.z), h3 = __float2bfloat16(v.w);
    __nv_bfloat16 l0 = __float2bfloat16(v.x - __bfloat162float(h0));
    __nv_bfloat16 l1 = __float2bfloat16(v.y - __bfloat162float(h1));
    __nv_bfloat16 l2 = __float2bfloat16(v.z - __bfloat162float(h2));
    __nv_bfloat16 l3 = __float2bfloat16(v.w - __bfloat162float(h3));
    __nv_bfloat162* Ah = (__nv_bfloat162*)g_Ah;
    __nv_bfloat162* Al = (__nv_bfloat162*)g_Al;
    __nv_bfloat162 p;
    p.x = h0; p.y = h1; Ah[idx * 2]     = p;
    p.x = h2; p.y = h3; Ah[idx * 2 + 1] = p;
    p.x = l0; p.y = l1; Al[idx * 2]     = p;
    p.x = l2; p.y = l3; Al[idx * 2 + 1] = p;
}

// ===========================================================================
// Kernel: convert MU -> bf16 hi/lo, fused with m2[c] = ||mu_c||^2
// ===========================================================================
__global__ __launch_bounds__(128) void k_convMU(const float* __restrict__ MU) {
    const int c = blockIdx.x;
    const size_t base = (size_t)c * DDIM;
    float s = 0.f;
    #pragma unroll
    for (int j = 0; j < 4; j++) {
        int d = threadIdx.x + j * 128;
        float x = MU[base + d];
        __nv_bfloat16 h = __float2bfloat16(x);
        __nv_bfloat16 l = __float2bfloat16(x - __bfloat162float(h));
        g_Bh[base + d] = h;
        g_Bl[base + d] = l;
        s = fmaf(x, x, s);
    }
    #pragma unroll
    for (int o = 16; o; o >>= 1) s += __shfl_xor_sync(0xffffffffu, s, o);
    __shared__ float sm[4];
    if ((threadIdx.x & 31) == 0) sm[threadIdx.x >> 5] = s;
    __syncthreads();
    if (threadIdx.x == 0) g_m2[c] = sm[0] + sm[1] + sm[2] + sm[3];
}

// ===========================================================================
// Hybrid GEMM: S[i][j] = 2*(x_i . mu_j) - m2[j]
//   blockIdx.x <  13 : tensor path (bf16 3-product split, HMMA pipe)
//   blockIdx.x >= 13 : exact fp32 SIMT path (FMA pipe)
// Both CTA types co-reside per SM (2 CTAs/SM) and use disjoint exec pipes.
// ===========================================================================
__device__ __forceinline__ void load_chunk(uint32_t stb, int t,
                                           int bm, int bn, int tid) {
    const int phase = t >> 3;
    const int koff  = (t & 7) * BK;
    const __nv_bfloat16* A = (phase == 1) ? g_Al : g_Ah;
    const __nv_bfloat16* B = (phase == 2) ? g_Bl : g_Bh;
    const uint32_t bs = stb + TILE_BYTES;
    #pragma unroll
    for (int i = 0; i < 4; i++) {
        int q = tid + i * 256;
        int r = q >> 3, c = q & 7;
        uint32_t off = r * 128 + ((c * 16) ^ ((r & 7) << 4));
        cp16(stb + off, A + (size_t)(bm + r) * DDIM + koff + c * 8);
    }
    #pragma unroll
    for (int i = 0; i < 4; i++) {
        int q = tid + i * 256;
        int r = q >> 3, c = q & 7;
        uint32_t off = r * 128 + ((c * 16) ^ ((r & 7) << 4));
        cp16(bs + off, B + (size_t)(bn + r) * DDIM + koff + c * 8);
    }
}

__global__ __launch_bounds__(256, 2)
void k_hyb(float* __restrict__ S, const float* __restrict__ X,
           const float* __restrict__ MU) {
    extern __shared__ char smem[];
    const int tid = threadIdx.x;
    const int bm = blockIdx.y * BM;
    const int bn = blockIdx.x * BN;

    if (blockIdx.x < TENS_TILES) {
        // ================= tensor path (round-7 proven config) =============
        const uint32_t sb = smem_u32(smem);
        const int wid = tid >> 5, l = tid & 31;
        const int wm = (wid & 1) * 64;
        const int wn = (wid >> 1) * 32;

        float acc[4][4][4];
        #pragma unroll
        for (int i = 0; i < 4; i++)
            #pragma unroll
            for (int j = 0; j < 4; j++)
                #pragma unroll
                for (int k = 0; k < 4; k++) acc[i][j][k] = 0.f;

        const uint32_t sw   = (uint32_t)(l & 7) << 4;
        const int rowA = wm + (l & 15);
        const uint32_t aColSel = ((uint32_t)(l >> 4)) << 4;
        const int rowB = wn + ((l >> 4) << 3) + (l & 7);
        const uint32_t bColSel = ((uint32_t)((l >> 3) & 1)) << 4;

        load_chunk(sb + 0 * STAGE_BYTES, 0, bm, bn, tid); CP_COMMIT();
        load_chunk(sb + 1 * STAGE_BYTES, 1, bm, bn, tid); CP_COMMIT();

        int rs = 0, ws = 2;
        for (int t = 0; t < KCHUNKS; t++) {
            CP_WAIT1();
            __syncthreads();

            if (t + 2 < KCHUNKS) load_chunk(sb + ws * STAGE_BYTES, t + 2, bm, bn, tid);
            CP_COMMIT();

            const uint32_t as = sb + rs * STAGE_BYTES;
            const uint32_t bs = as + TILE_BYTES;

            #pragma unroll
            for (int ks = 0; ks < 4; ks++) {
                const uint32_t kb = (uint32_t)ks * 32;
                uint32_t a[4][4], b[2][4];
                #pragma unroll
                for (int bt = 0; bt < 2; bt++)
                    ldsm4(b[bt], bs + (uint32_t)(rowB + bt * 16) * 128 + ((kb + bColSel) ^ sw));
                #pragma unroll
                for (int mt = 0; mt < 4; mt++)
                    ldsm4(a[mt], as + (uint32_t)(rowA + mt * 16) * 128 + ((kb + aColSel) ^ sw));
                #pragma unroll
                for (int mt = 0; mt < 4; mt++) {
                    mma16816(acc[mt][0], a[mt], &b[0][0]);
                    mma16816(acc[mt][1], a[mt], &b[0][2]);
                    mma16816(acc[mt][2], a[mt], &b[1][0]);
                    mma16816(acc[mt][3], a[mt], &b[1][2]);
                }
            }

            rs = (rs == 2) ? 0 : rs + 1;
            ws = (ws == 2) ? 0 : ws + 1;
        }

        const int cbase = bn + wn + (l & 3) * 2;
        float m2v[4][2];
        #pragma unroll
        for (int nt = 0; nt < 4; nt++) {
            m2v[nt][0] = g_m2[cbase + nt * 8];
            m2v[nt][1] = g_m2[cbase + nt * 8 + 1];
        }
        const int rbase = bm + wm + (l >> 2);
        #pragma unroll
        for (int mt = 0; mt < 4; mt++) {
            #pragma unroll
            for (int nt = 0; nt < 4; nt++) {
                float2 v0, v1;
                v0.x = 2.f * acc[mt][nt][0] - m2v[nt][0];
                v0.y = 2.f * acc[mt][nt][1] - m2v[nt][1];
                v1.x = 2.f * acc[mt][nt][2] - m2v[nt][0];
                v1.y = 2.f * acc[mt][nt][3] - m2v[nt][1];
                const int r = rbase + mt * 16;
                const int c = cbase + nt * 8;
                *(float2*)(S + (size_t)r * CCLS + c)       = v0;
                *(float2*)(S + (size_t)(r + 8) * CCLS + c) = v1;
            }
        }
    } else {
        // ================= exact fp32 SIMT path (round-4 proven) ===========
        float* AsF = (float*)smem;                 // [2][FBK][BM]
        float* BsF = AsF + 2 * FBK * BM;           // [2][FBK][BN]
        #define ASF(b,k,m) AsF[((b) * FBK + (k)) * BM + (m)]
        #define BSF(b,k,n) BsF[((b) * FBK + (k)) * BN + (n)]

        const int tx = tid & 15;
        const int ty = tid >> 4;
        const int lr = tid >> 2;
        const int lc = (tid & 3) << 2;

        const float* xp = X  + (size_t)(bm + lr) * DDIM + lc;
        const float* bp = MU + (size_t)(bn + lr) * DDIM + lc;

        float acc[8][8];
        #pragma unroll
        for (int i = 0; i < 8; i++)
            #pragma unroll
            for (int j = 0; j < 8; j++) acc[i][j] = 0.f;

        float4 ra0 = *(const float4*)(xp);
        float4 ra1 = *(const float4*)(xp + (size_t)64 * DDIM);
        float4 rb0 = *(const float4*)(bp);
        float4 rb1 = *(const float4*)(bp + (size_t)64 * DDIM);

        ASF(0,lc+0,lr)    = ra0.x; ASF(0,lc+1,lr)    = ra0.y;
        ASF(0,lc+2,lr)    = ra0.z; ASF(0,lc+3,lr)    = ra0.w;
        ASF(0,lc+0,lr+64) = ra1.x; ASF(0,lc+1,lr+64) = ra1.y;
        ASF(0,lc+2,lr+64) = ra1.z; ASF(0,lc+3,lr+64) = ra1.w;
        BSF(0,lc+0,lr)    = rb0.x; BSF(0,lc+1,lr)    = rb0.y;
        BSF(0,lc+2,lr)    = rb0.z; BSF(0,lc+3,lr)    = rb0.w;
        BSF(0,lc+0,lr+64) = rb1.x; BSF(0,lc+1,lr+64) = rb1.y;
        BSF(0,lc+2,lr+64) = rb1.z; BSF(0,lc+3,lr+64) = rb1.w;
        __syncthreads();

        int buf = 0;
        for (int k0 = 0; k0 < DDIM; k0 += FBK) {
            const bool more = (k0 + FBK) < DDIM;
            if (more) {
                const float* xn = xp + k0 + FBK;
                const float* bq = bp + k0 + FBK;
                ra0 = *(const float4*)(xn);
                ra1 = *(const float4*)(xn + (size_t)64 * DDIM);
                rb0 = *(const float4*)(bq);
                rb1 = *(const float4*)(bq + (size_t)64 * DDIM);
            }

            #pragma unroll
            for (int kk = 0; kk < FBK; kk++) {
                float4 a0 = *(const float4*)&ASF(buf, kk, ty * 8);
                float4 a1 = *(const float4*)&ASF(buf, kk, ty * 8 + 4);
                float4 b0 = *(const float4*)&BSF(buf, kk, tx * 8);
                float4 b1 = *(const float4*)&BSF(buf, kk, tx * 8 + 4);
                float a[8] = {a0.x, a0.y, a0.z, a0.w, a1.x, a1.y, a1.z, a1.w};
                float b[8] = {b0.x, b0.y, b0.z, b0.w, b1.x, b1.y, b1.z, b1.w};
                #pragma unroll
                for (int i = 0; i < 8; i++)
                    #pragma unroll
                    for (int j = 0; j < 8; j++)
                        acc[i][j] = fmaf(a[i], b[j], acc[i][j]);
            }

            if (more) {
                const int nb = buf ^ 1;
                ASF(nb,lc+0,lr)    = ra0.x; ASF(nb,lc+1,lr)    = ra0.y;
                ASF(nb,lc+2,lr)    = ra0.z; ASF(nb,lc+3,lr)    = ra0.w;
                ASF(nb,lc+0,lr+64) = ra1.x; ASF(nb,lc+1,lr+64) = ra1.y;
                ASF(nb,lc+2,lr+64) = ra1.z; ASF(nb,lc+3,lr+64) = ra1.w;
                BSF(nb,lc+0,lr)    = rb0.x; BSF(nb,lc+1,lr)    = rb0.y;
                BSF(nb,lc+2,lr)    = rb0.z; BSF(nb,lc+3,lr)    = rb0.w;
                BSF(nb,lc+0,lr+64) = rb1.x; BSF(nb,lc+1,lr+64) = rb1.y;
                BSF(nb,lc+2,lr+64) = rb1.z; BSF(nb,lc+3,lr+64) = rb1.w;
                __syncthreads();
                buf = nb;
            }
        }

        float m2c[8];
        #pragma unroll
        for (int j = 0; j < 8; j++) m2c[j] = g_m2[bn + tx * 8 + j];

        #pragma unroll
        for (int i = 0; i < 8; i++) {
            float* op = S + (size_t)(bm + ty * 8 + i) * CCLS + bn + tx * 8;
            float4 o0, o1;
            o0.x = 2.f * acc[i][0] - m2c[0];
            o0.y = 2.f * acc[i][1] - m2c[1];
            o0.z = 2.f * acc[i][2] - m2c[2];
            o0.w = 2.f * acc[i][3] - m2c[3];
            o1.x = 2.f * acc[i][4] - m2c[4];
            o1.y = 2.f * acc[i][5] - m2c[5];
            o1.z = 2.f * acc[i][6] - m2c[6];
            o1.w = 2.f * acc[i][7] - m2c[7];
            *(float4*)op       = o0;
            *(float4*)(op + 4) = o1;
        }
        #undef ASF
        #undef BSF
    }
}

// ===========================================================================
// Kernel: per-row masked softmax, in place on S
// ===========================================================================
__device__ __forceinline__ float block_red(float v, int mode, float* sred, int tid) {
    #pragma unroll
    for (int o = 16; o; o >>= 1) {
        float t = __shfl_xor_sync(0xffffffffu, v, o);
        v = (mode == 0) ? fminf(v, t) : (mode == 1) ? fmaxf(v, t) : (v + t);
    }
    __syncthreads();
    if ((tid & 31) == 0) sred[tid >> 5] = v;
    __syncthreads();
    float r;
    if (mode == 0) {
        r = fminf(fminf(fminf(sred[0], sred[1]), fminf(sred[2], sred[3])),
                  fminf(fminf(sred[4], sred[5]), fminf(sred[6], sred[7])));
    } else if (mode == 1) {
        r = fmaxf(fmaxf(fmaxf(sred[0], sred[1]), fmaxf(sred[2], sred[3])),
                  fmaxf(fmaxf(sred[4], sred[5]), fmaxf(sred[6], sred[7])));
    } else {
        r = ((sred[0] + sred[1]) + (sred[2] + sred[3])) +
            ((sred[4] + sred[5]) + (sred[6] + sred[7]));
    }
    return r;
}

__global__ __launch_bounds__(256) void k_softmax(float* __restrict__ S,
                                                 const float* __restrict__ cK) {
    __shared__ float sred[8];
    const int row = blockIdx.x;
    const int tid = threadIdx.x;
    float4* sp = (float4*)(S + (size_t)row * CCLS);
    const float4* cp = (const float4*)cK;

    float4 v0 = sp[tid];
    float4 v1 = sp[tid + 256];
    float4 c0 = cp[tid];
    float4 c1 = cp[tid + 256];

    float mn = fminf(fminf(fminf(v0.x, v0.y), fminf(v0.z, v0.w)),
                     fminf(fminf(v1.x, v1.y), fminf(v1.z, v1.w)));
    mn = block_red(mn, 0, sred, tid);
    const float mval = mn - 1.f;

    v0.x = (c0.x == 0.f) ? mval : v0.x;
    v0.y = (c0.y == 0.f) ? mval : v0.y;
    v0.z = (c0.z == 0.f) ? mval : v0.z;
    v0.w = (c0.w == 0.f) ? mval : v0.w;
    v1.x = (c1.x == 0.f) ? mval : v1.x;
    v1.y = (c1.y == 0.f) ? mval : v1.y;
    v1.z = (c1.z == 0.f) ? mval : v1.z;
    v1.w = (c1.w == 0.f) ? mval : v1.w;

    float mx = fmaxf(fmaxf(fmaxf(v0.x, v0.y), fmaxf(v0.z, v0.w)),
                     fmaxf(fmaxf(v1.x, v1.y), fmaxf(v1.z, v1.w)));
    mx = block_red(mx, 1, sred, tid);

    float4 e0, e1;
    e0.x = __expf(v0.x - mx); e0.y = __expf(v0.y - mx);
    e0.z = __expf(v0.z - mx); e0.w = __expf(v0.w - mx);
    e1.x = __expf(v1.x - mx); e1.y = __expf(v1.y - mx);
    e1.z = __expf(v1.z - mx); e1.w = __expf(v1.w - mx);
    float sum = ((e0.x + e0.y) + (e0.z + e0.w)) + ((e1.x + e1.y) + (e1.z + e1.w));
    sum = block_red(sum, 2, sred, tid);
    const float inv = 1.f / sum;

    e0.x *= inv; e0.y *= inv; e0.z *= inv; e0.w *= inv;
    e1.x *= inv; e1.y *= inv; e1.z *= inv; e1.w *= inv;
    sp[tid]       = e0;
    sp[tid + 256] = e1;
}

// ===========================================================================
extern "C" void kernel_launch(void* const* d_in, const int* in_sizes, int n_in,
                              void* d_out, int out_size) {
    const float* X  = (const float*)d_in[0];   // (N, D) fp32
    const float* MU = (const float*)d_in[1];   // (C, D) fp32
    const float* cK = (const float*)d_in[2];   // (C,)   fp32
    float* out = (float*)d_out;                // (N, C) fp32

    cudaFuncSetAttribute(k_hyb, cudaFuncAttributeMaxDynamicSharedMemorySize, SMEM_TOTAL);

    k_convX<<<(NROWS * DDIM) / 4 / 256, 256>>>(X);
    k_convMU<<<CCLS, 128>>>(MU);

    dim3 grid(NTILES, NROWS / BM);             // (16, 256), x-fastest -> mixed waves
    k_hyb<<<grid, 256, SMEM_TOTAL>>>(out, X, MU);

    k_softmax<<<NROWS, 256>>>(out, cK);
}

// round 10
// speedup vs baseline: 1.5921x; 1.5921x over previous
#include <cuda_runtime.h>
#include <cuda_bf16.h>
#include <cstdint>

#define NROWS 32768
#define CCLS  2048
#define DDIM  512

// ---- tensor-path tiling (round-7 proven config) ----
#define BM 128
#define BN 128
#define BK 64                    // bf16 elems per chunk (128B per row)
#define KCHUNKS 24               // 3 products x (512/64)
#define TILE_BYTES 16384         // 128 rows x 128B
#define STAGE_BYTES (2 * TILE_BYTES)
#define NSTAGES 3
#define SMEM_TOTAL  (NSTAGES * STAGE_BYTES)   // 98304

#define NEGHUGE -3.0e38f

// ---- scratch (__device__ globals; no cudaMalloc allowed) ----
__device__ __nv_bfloat16 g_Ah[(size_t)NROWS * DDIM];
__device__ __nv_bfloat16 g_Al[(size_t)NROWS * DDIM];
__device__ __nv_bfloat16 g_Bh[(size_t)CCLS * DDIM];   // compacted (visited only)
__device__ __nv_bfloat16 g_Bl[(size_t)CCLS * DDIM];   // compacted
__device__ float g_m2c[CCLS];                          // compacted ||mu||^2
__device__ int   g_pos[CCLS];                          // class -> compacted slot
__device__ int   g_idx[CCLS];                          // compacted slot -> class
__device__ int   g_V;                                  // number of visited classes

// ===========================================================================
// PTX helpers (all supported on plain sm_103 target)
// ===========================================================================
__device__ __forceinline__ uint32_t smem_u32(const void* p) {
    uint32_t a;
    asm("{ .reg .u64 t; cvta.to.shared.u64 t, %1; cvt.u32.u64 %0, t; }" : "=r"(a) : "l"(p));
    return a;
}

__device__ __forceinline__ void cp16(uint32_t dst, const void* src) {
    asm volatile("cp.async.cg.shared.global.L2::128B [%0], [%1], 16;" :: "r"(dst), "l"(src));
}
#define CP_COMMIT() asm volatile("cp.async.commit_group;" ::: "memory")
#define CP_WAIT1()  asm volatile("cp.async.wait_group 1;" ::: "memory")

__device__ __forceinline__ void ldsm4(uint32_t* r, uint32_t addr) {
    asm volatile("ldmatrix.sync.aligned.m8n8.x4.shared.b16 {%0,%1,%2,%3}, [%4];"
                 : "=r"(r[0]), "=r"(r[1]), "=r"(r[2]), "=r"(r[3]) : "r"(addr));
}

__device__ __forceinline__ void mma16816(float* d, const uint32_t* a, const uint32_t* b) {
    asm volatile("mma.sync.aligned.m16n8k16.row.col.f32.bf16.bf16.f32 "
                 "{%0,%1,%2,%3}, {%4,%5,%6,%7}, {%8,%9}, {%0,%1,%2,%3};"
                 : "+f"(d[0]), "+f"(d[1]), "+f"(d[2]), "+f"(d[3])
                 : "r"(a[0]), "r"(a[1]), "r"(a[2]), "r"(a[3]), "r"(b[0]), "r"(b[1]));
}

// ===========================================================================
// Kernel: prefix scan over visited flags -> pos / idx / V
// ===========================================================================
__global__ __launch_bounds__(1024) void k_scan(const float* __restrict__ cK) {
    __shared__ int s[1024];
    const int t = threadIdx.x;
    const int f0 = (cK[2 * t]     != 0.f) ? 1 : 0;
    const int f1 = (cK[2 * t + 1] != 0.f) ? 1 : 0;
    const int p = f0 + f1;
    int v = p;
    s[t] = v;
    __syncthreads();
    #pragma unroll
    for (int off = 1; off < 1024; off <<= 1) {
        int add = (t >= off) ? s[t - off] : 0;
        __syncthreads();
        v += add;
        s[t] = v;
        __syncthreads();
    }
    const int excl = v - p;                  // exclusive prefix (pairs)
    g_pos[2 * t]     = excl;
    g_pos[2 * t + 1] = excl + f0;
    if (f0) g_idx[excl]      = 2 * t;
    if (f1) g_idx[excl + f0] = 2 * t + 1;
    if (t == 1023) g_V = v;
}

// ===========================================================================
// Kernel: convert X -> bf16 hi/lo
// ===========================================================================
__global__ __launch_bounds__(256) void k_convX(const float* __restrict__ X) {
    const int idx = blockIdx.x * 256 + threadIdx.x;        // float4 index
    float4 v = ((const float4*)X)[idx];
    __nv_bfloat16 h0 = __float2bfloat16(v.x), h1 = __float2bfloat16(v.y);
    __nv_bfloat16 h2 = __float2bfloat16(v.z), h3 = __float2bfloat16(v.w);
    __nv_bfloat16 l0 = __float2bfloat16(v.x - __bfloat162float(h0));
    __nv_bfloat16 l1 = __float2bfloat16(v.y - __bfloat162float(h1));
    __nv_bfloat16 l2 = __float2bfloat16(v.z - __bfloat162float(h2));
    __nv_bfloat16 l3 = __float2bfloat16(v.w - __bfloat162float(h3));
    __nv_bfloat162* Ah = (__nv_bfloat162*)g_Ah;
    __nv_bfloat162* Al = (__nv_bfloat162*)g_Al;
    __nv_bfloat162 p;
    p.x = h0; p.y = h1; Ah[idx * 2]     = p;
    p.x = h2; p.y = h3; Ah[idx * 2 + 1] = p;
    p.x = l0; p.y = l1; Al[idx * 2]     = p;
    p.x = l2; p.y = l3; Al[idx * 2 + 1] = p;
}

// ===========================================================================
// Kernel: convert visited MU rows -> compacted bf16 hi/lo + m2
// ===========================================================================
__global__ __launch_bounds__(128) void k_convMU(const float* __restrict__ MU,
                                                const float* __restrict__ cK) {
    const int c = blockIdx.x;
    if (cK[c] == 0.f) return;                 // unvisited: skip entirely
    const int p = g_pos[c];
    const size_t src = (size_t)c * DDIM;
    const size_t dst = (size_t)p * DDIM;
    float s = 0.f;
    #pragma unroll
    for (int j = 0; j < 4; j++) {
        int d = threadIdx.x + j * 128;
        float x = MU[src + d];
        __nv_bfloat16 h = __float2bfloat16(x);
        __nv_bfloat16 l = __float2bfloat16(x - __bfloat162float(h));
        g_Bh[dst + d] = h;
        g_Bl[dst + d] = l;
        s = fmaf(x, x, s);
    }
    #pragma unroll
    for (int o = 16; o; o >>= 1) s += __shfl_xor_sync(0xffffffffu, s, o);
    __shared__ float sm[4];
    if ((threadIdx.x & 31) == 0) sm[threadIdx.x >> 5] = s;
    __syncthreads();
    if (threadIdx.x == 0) g_m2c[p] = sm[0] + sm[1] + sm[2] + sm[3];
}

// ===========================================================================
// Kernel: HMMA GEMM over COMPACTED columns, scatter-store to full S.
// S[i][idx[p]] = 2*(x_i . mu_idx[p]) - m2[idx[p]]
// ===========================================================================
__device__ __forceinline__ void load_chunk(uint32_t stb, int t,
                                           int bm, int bn, int tid) {
    const int phase = t >> 3;
    const int koff  = (t & 7) * BK;
    const __nv_bfloat16* A = (phase == 1) ? g_Al : g_Ah;
    const __nv_bfloat16* B = (phase == 2) ? g_Bl : g_Bh;
    const uint32_t bs = stb + TILE_BYTES;
    #pragma unroll
    for (int i = 0; i < 4; i++) {
        int q = tid + i * 256;
        int r = q >> 3, c = q & 7;
        uint32_t off = r * 128 + ((c * 16) ^ ((r & 7) << 4));
        cp16(stb + off, A + (size_t)(bm + r) * DDIM + koff + c * 8);
    }
    #pragma unroll
    for (int i = 0; i < 4; i++) {
        int q = tid + i * 256;
        int r = q >> 3, c = q & 7;
        uint32_t off = r * 128 + ((c * 16) ^ ((r & 7) << 4));
        cp16(bs + off, B + (size_t)(bn + r) * DDIM + koff + c * 8);
    }
}

__global__ __launch_bounds__(256, 2) void k_gemm_mma(float* __restrict__ S) {
    const int bn = blockIdx.x * BN;
    const int V = g_V;
    if (bn >= V) return;                      // tile fully in pad region

    extern __shared__ char smem[];
    const uint32_t sb = smem_u32(smem);
    const int tid = threadIdx.x;
    const int wid = tid >> 5, l = tid & 31;
    const int bm = blockIdx.y * BM;
    const int wm = (wid & 1) * 64;
    const int wn = (wid >> 1) * 32;

    float acc[4][4][4];
    #pragma unroll
    for (int i = 0; i < 4; i++)
        #pragma unroll
        for (int j = 0; j < 4; j++)
            #pragma unroll
            for (int k = 0; k < 4; k++) acc[i][j][k] = 0.f;

    const uint32_t sw   = (uint32_t)(l & 7) << 4;
    const int rowA = wm + (l & 15);
    const uint32_t aColSel = ((uint32_t)(l >> 4)) << 4;
    const int rowB = wn + ((l >> 4) << 3) + (l & 7);
    const uint32_t bColSel = ((uint32_t)((l >> 3) & 1)) << 4;

    load_chunk(sb + 0 * STAGE_BYTES, 0, bm, bn, tid); CP_COMMIT();
    load_chunk(sb + 1 * STAGE_BYTES, 1, bm, bn, tid); CP_COMMIT();

    int rs = 0, ws = 2;
    for (int t = 0; t < KCHUNKS; t++) {
        CP_WAIT1();
        __syncthreads();

        if (t + 2 < KCHUNKS) load_chunk(sb + ws * STAGE_BYTES, t + 2, bm, bn, tid);
        CP_COMMIT();

        const uint32_t as = sb + rs * STAGE_BYTES;
        const uint32_t bs = as + TILE_BYTES;

        #pragma unroll
        for (int ks = 0; ks < 4; ks++) {
            const uint32_t kb = (uint32_t)ks * 32;
            uint32_t a[4][4], b[2][4];
            #pragma unroll
            for (int bt = 0; bt < 2; bt++)
                ldsm4(b[bt], bs + (uint32_t)(rowB + bt * 16) * 128 + ((kb + bColSel) ^ sw));
            #pragma unroll
            for (int mt = 0; mt < 4; mt++)
                ldsm4(a[mt], as + (uint32_t)(rowA + mt * 16) * 128 + ((kb + aColSel) ^ sw));
            #pragma unroll
            for (int mt = 0; mt < 4; mt++) {
                mma16816(acc[mt][0], a[mt], &b[0][0]);
                mma16816(acc[mt][1], a[mt], &b[0][2]);
                mma16816(acc[mt][2], a[mt], &b[1][0]);
                mma16816(acc[mt][3], a[mt], &b[1][2]);
            }
        }

        rs = (rs == 2) ? 0 : rs + 1;
        ws = (ws == 2) ? 0 : ws + 1;
    }

    // epilogue: scatter-store 2*d - m2 into real class columns
    const int ccomp = bn + wn + (l & 3) * 2;          // compacted col of frag .x
    int   real0[4], real1[4];
    float m20[4], m21[4];
    bool  ok0[4], ok1[4];
    #pragma unroll
    for (int nt = 0; nt < 4; nt++) {
        const int c0 = ccomp + nt * 8, c1 = c0 + 1;
        ok0[nt] = (c0 < V); ok1[nt] = (c1 < V);
        real0[nt] = ok0[nt] ? g_idx[c0] : 0;
        real1[nt] = ok1[nt] ? g_idx[c1] : 0;
        m20[nt] = ok0[nt] ? g_m2c[c0] : 0.f;
        m21[nt] = ok1[nt] ? g_m2c[c1] : 0.f;
    }
    const int rbase = bm + wm + (l >> 2);
    #pragma unroll
    for (int mt = 0; mt < 4; mt++) {
        const int r0 = rbase + mt * 16;
        const int r1 = r0 + 8;
        #pragma unroll
        for (int nt = 0; nt < 4; nt++) {
            if (ok0[nt]) {
                S[(size_t)r0 * CCLS + real0[nt]] = 2.f * acc[mt][nt][0] - m20[nt];
                S[(size_t)r1 * CCLS + real0[nt]] = 2.f * acc[mt][nt][2] - m20[nt];
            }
            if (ok1[nt]) {
                S[(size_t)r0 * CCLS + real1[nt]] = 2.f * acc[mt][nt][1] - m21[nt];
                S[(size_t)r1 * CCLS + real1[nt]] = 2.f * acc[mt][nt][3] - m21[nt];
            }
        }
    }
}

// ===========================================================================
// Kernel: per-row masked softmax, in place on S.
// Masked (cK==0) columns never read (contain poison) -> output exactly 0,
// matching the reference, whose exp(min-1-max) underflows to 0 in fp32.
// ===========================================================================
__device__ __forceinline__ float block_red(float v, int mode, float* sred, int tid) {
    #pragma unroll
    for (int o = 16; o; o >>= 1) {
        float t = __shfl_xor_sync(0xffffffffu, v, o);
        v = (mode == 1) ? fmaxf(v, t) : (v + t);
    }
    __syncthreads();
    if ((tid & 31) == 0) sred[tid >> 5] = v;
    __syncthreads();
    float r;
    if (mode == 1) {
        r = fmaxf(fmaxf(fmaxf(sred[0], sred[1]), fmaxf(sred[2], sred[3])),
                  fmaxf(fmaxf(sred[4], sred[5]), fmaxf(sred[6], sred[7])));
    } else {
        r = ((sred[0] + sred[1]) + (sred[2] + sred[3])) +
            ((sred[4] + sred[5]) + (sred[6] + sred[7]));
    }
    return r;
}

__global__ __launch_bounds__(256) void k_softmax(float* __restrict__ S,
                                                 const float* __restrict__ cK) {
    __shared__ float sred[8];
    const int row = blockIdx.x;
    const int tid = threadIdx.x;
    float4* sp = (float4*)(S + (size_t)row * CCLS);
    const float4* cp = (const float4*)cK;

    float4 v0 = sp[tid];
    float4 v1 = sp[tid + 256];
    float4 c0 = cp[tid];
    float4 c1 = cp[tid + 256];

    // mask unvisited (also removes poison values from unwritten columns)
    v0.x = (c0.x == 0.f) ? NEGHUGE : v0.x;
    v0.y = (c0.y == 0.f) ? NEGHUGE : v0.y;
    v0.z = (c0.z == 0.f) ? NEGHUGE : v0.z;
    v0.w = (c0.w == 0.f) ? NEGHUGE : v0.w;
    v1.x = (c1.x == 0.f) ? NEGHUGE : v1.x;
    v1.y = (c1.y == 0.f) ? NEGHUGE : v1.y;
    v1.z = (c1.z == 0.f) ? NEGHUGE : v1.z;
    v1.w = (c1.w == 0.f) ? NEGHUGE : v1.w;

    float mx = fmaxf(fmaxf(fmaxf(v0.x, v0.y), fmaxf(v0.z, v0.w)),
                     fmaxf(fmaxf(v1.x, v1.y), fmaxf(v1.z, v1.w)));
    mx = block_red(mx, 1, sred, tid);

    float4 e0, e1;
    e0.x = __expf(v0.x - mx); e0.y = __expf(v0.y - mx);
    e0.z = __expf(v0.z - mx); e0.w = __expf(v0.w - mx);
    e1.x = __expf(v1.x - mx); e1.y = __expf(v1.y - mx);
    e1.z = __expf(v1.z - mx); e1.w = __expf(v1.w - mx);
    float sum = ((e0.x + e0.y) + (e0.z + e0.w)) + ((e1.x + e1.y) + (e1.z + e1.w));
    sum = block_red(sum, 2, sred, tid);
    const float inv = 1.f / sum;

    e0.x *= inv; e0.y *= inv; e0.z *= inv; e0.w *= inv;
    e1.x *= inv; e1.y *= inv; e1.z *= inv; e1.w *= inv;
    sp[tid]       = e0;
    sp[tid + 256] = e1;
}

// ===========================================================================
extern "C" void kernel_launch(void* const* d_in, const int* in_sizes, int n_in,
                              void* d_out, int out_size) {
    const float* X  = (const float*)d_in[0];   // (N, D) fp32
    const float* MU = (const float*)d_in[1];   // (C, D) fp32
    const float* cK = (const float*)d_in[2];   // (C,)   fp32
    float* out = (float*)d_out;                // (N, C) fp32

    cudaFuncSetAttribute(k_gemm_mma, cudaFuncAttributeMaxDynamicSharedMemorySize, SMEM_TOTAL);

    k_scan<<<1, 1024>>>(cK);
    k_convX<<<(NROWS * DDIM) / 4 / 256, 256>>>(X);
    k_convMU<<<CCLS, 128>>>(MU, cK);

    dim3 grid(CCLS / BN, NROWS / BM);          // (16, 256); pad tiles exit early
    k_gemm_mma<<<grid, 256, SMEM_TOTAL>>>(out);

    k_softmax<<<NROWS, 256>>>(out, cK);
}

// round 11
// speedup vs baseline: 1.7919x; 1.1255x over previous
#include <cuda_runtime.h>
#include <cuda_bf16.h>
#include <cstdint>

#define NROWS 32768
#define CCLS  2048
#define DDIM  512

// ---- tensor-path tiling (round-7 proven config) ----
#define BM 128
#define BN 128
#define BK 64                    // bf16 elems per chunk (128B per row)
#define KCHUNKS 24               // 3 products x (512/64)
#define TILE_BYTES 16384         // 128 rows x 128B
#define STAGE_BYTES (2 * TILE_BYTES)
#define NSTAGES 3
#define SMEM_TOTAL  (NSTAGES * STAGE_BYTES)   // 98304

#define NEGHUGE -3.0e38f

// ---- scratch (__device__ globals; no cudaMalloc allowed) ----
__device__ __nv_bfloat16 g_Ah[(size_t)NROWS * DDIM];
__device__ __nv_bfloat16 g_Al[(size_t)NROWS * DDIM];
__device__ __nv_bfloat16 g_Bh[(size_t)CCLS * DDIM];   // compacted (visited only)
__device__ __nv_bfloat16 g_Bl[(size_t)CCLS * DDIM];   // compacted
__device__ float g_m2c[CCLS];                          // compacted ||mu||^2
__device__ int   g_pos[CCLS];                          // class -> compacted slot
__device__ int   g_V;                                  // number of visited classes

// ===========================================================================
// PTX helpers (all supported on plain sm_103 target)
// ===========================================================================
__device__ __forceinline__ uint32_t smem_u32(const void* p) {
    uint32_t a;
    asm("{ .reg .u64 t; cvta.to.shared.u64 t, %1; cvt.u32.u64 %0, t; }" : "=r"(a) : "l"(p));
    return a;
}

__device__ __forceinline__ void cp16(uint32_t dst, const void* src) {
    asm volatile("cp.async.cg.shared.global.L2::128B [%0], [%1], 16;" :: "r"(dst), "l"(src));
}
#define CP_COMMIT() asm volatile("cp.async.commit_group;" ::: "memory")
#define CP_WAIT1()  asm volatile("cp.async.wait_group 1;" ::: "memory")

__device__ __forceinline__ void ldsm4(uint32_t* r, uint32_t addr) {
    asm volatile("ldmatrix.sync.aligned.m8n8.x4.shared.b16 {%0,%1,%2,%3}, [%4];"
                 : "=r"(r[0]), "=r"(r[1]), "=r"(r[2]), "=r"(r[3]) : "r"(addr));
}

__device__ __forceinline__ void mma16816(float* d, const uint32_t* a, const uint32_t* b) {
    asm volatile("mma.sync.aligned.m16n8k16.row.col.f32.bf16.bf16.f32 "
                 "{%0,%1,%2,%3}, {%4,%5,%6,%7}, {%8,%9}, {%0,%1,%2,%3};"
                 : "+f"(d[0]), "+f"(d[1]), "+f"(d[2]), "+f"(d[3])
                 : "r"(a[0]), "r"(a[1]), "r"(a[2]), "r"(a[3]), "r"(b[0]), "r"(b[1]));
}

// ===========================================================================
// Kernel: prefix scan over visited flags -> pos / V
// ===========================================================================
__global__ __launch_bounds__(1024) void k_scan(const float* __restrict__ cK) {
    __shared__ int s[1024];
    const int t = threadIdx.x;
    const int f0 = (cK[2 * t]     != 0.f) ? 1 : 0;
    const int f1 = (cK[2 * t + 1] != 0.f) ? 1 : 0;
    const int p = f0 + f1;
    int v = p;
    s[t] = v;
    __syncthreads();
    #pragma unroll
    for (int off = 1; off < 1024; off <<= 1) {
        int add = (t >= off) ? s[t - off] : 0;
        __syncthreads();
        v += add;
        s[t] = v;
        __syncthreads();
    }
    const int excl = v - p;                  // exclusive prefix (pairs)
    g_pos[2 * t]     = excl;
    g_pos[2 * t + 1] = excl + f0;
    if (t == 1023) g_V = v;
}

// ===========================================================================
// Kernel: convert X -> bf16 hi/lo
// ===========================================================================
__global__ __launch_bounds__(256) void k_convX(const float* __restrict__ X) {
    const int idx = blockIdx.x * 256 + threadIdx.x;        // float4 index
    float4 v = ((const float4*)X)[idx];
    __nv_bfloat16 h0 = __float2bfloat16(v.x), h1 = __float2bfloat16(v.y);
    __nv_bfloat16 h2 = __float2bfloat16(v.z), h3 = __float2bfloat16(v.w);
    __nv_bfloat16 l0 = __float2bfloat16(v.x - __bfloat162float(h0));
    __nv_bfloat16 l1 = __float2bfloat16(v.y - __bfloat162float(h1));
    __nv_bfloat16 l2 = __float2bfloat16(v.z - __bfloat162float(h2));
    __nv_bfloat16 l3 = __float2bfloat16(v.w - __bfloat162float(h3));
    __nv_bfloat162* Ah = (__nv_bfloat162*)g_Ah;
    __nv_bfloat162* Al = (__nv_bfloat162*)g_Al;
    __nv_bfloat162 p;
    p.x = h0; p.y = h1; Ah[idx * 2]     = p;
    p.x = h2; p.y = h3; Ah[idx * 2 + 1] = p;
    p.x = l0; p.y = l1; Al[idx * 2]     = p;
    p.x = l2; p.y = l3; Al[idx * 2 + 1] = p;
}

// ===========================================================================
// Kernel: convert visited MU rows -> compacted bf16 hi/lo + m2
// ===========================================================================
__global__ __launch_bounds__(128) void k_convMU(const float* __restrict__ MU,
                                                const float* __restrict__ cK) {
    const int c = blockIdx.x;
    if (cK[c] == 0.f) return;                 // unvisited: skip entirely
    const int p = g_pos[c];
    const size_t src = (size_t)c * DDIM;
    const size_t dst = (size_t)p * DDIM;
    float s = 0.f;
    #pragma unroll
    for (int j = 0; j < 4; j++) {
        int d = threadIdx.x + j * 128;
        float x = MU[src + d];
        __nv_bfloat16 h = __float2bfloat16(x);
        __nv_bfloat16 l = __float2bfloat16(x - __bfloat162float(h));
        g_Bh[dst + d] = h;
        g_Bl[dst + d] = l;
        s = fmaf(x, x, s);
    }
    #pragma unroll
    for (int o = 16; o; o >>= 1) s += __shfl_xor_sync(0xffffffffu, s, o);
    __shared__ float sm[4];
    if ((threadIdx.x & 31) == 0) sm[threadIdx.x >> 5] = s;
    __syncthreads();
    if (threadIdx.x == 0) g_m2c[p] = sm[0] + sm[1] + sm[2] + sm[3];
}

// ===========================================================================
// Kernel: HMMA GEMM over COMPACTED columns; output stays COMPACTED (coalesced).
// S[i][p] = 2*(x_i . mu_{idx[p]}) - m2c[p],  p in [0, V)
// ===========================================================================
__device__ __forceinline__ void load_chunk(uint32_t stb, int t,
                                           int bm, int bn, int tid) {
    const int phase = t >> 3;
    const int koff  = (t & 7) * BK;
    const __nv_bfloat16* A = (phase == 1) ? g_Al : g_Ah;
    const __nv_bfloat16* B = (phase == 2) ? g_Bl : g_Bh;
    const uint32_t bs = stb + TILE_BYTES;
    #pragma unroll
    for (int i = 0; i < 4; i++) {
        int q = tid + i * 256;
        int r = q >> 3, c = q & 7;
        uint32_t off = r * 128 + ((c * 16) ^ ((r & 7) << 4));
        cp16(stb + off, A + (size_t)(bm + r) * DDIM + koff + c * 8);
    }
    #pragma unroll
    for (int i = 0; i < 4; i++) {
        int q = tid + i * 256;
        int r = q >> 3, c = q & 7;
        uint32_t off = r * 128 + ((c * 16) ^ ((r & 7) << 4));
        cp16(bs + off, B + (size_t)(bn + r) * DDIM + koff + c * 8);
    }
}

__global__ __launch_bounds__(256, 2) void k_gemm_mma(float* __restrict__ S) {
    const int bn = blockIdx.x * BN;
    const int V = g_V;
    if (bn >= V) return;                      // tile fully in pad region

    extern __shared__ char smem[];
    const uint32_t sb = smem_u32(smem);
    const int tid = threadIdx.x;
    const int wid = tid >> 5, l = tid & 31;
    const int bm = blockIdx.y * BM;
    const int wm = (wid & 1) * 64;
    const int wn = (wid >> 1) * 32;

    float acc[4][4][4];
    #pragma unroll
    for (int i = 0; i < 4; i++)
        #pragma unroll
        for (int j = 0; j < 4; j++)
            #pragma unroll
            for (int k = 0; k < 4; k++) acc[i][j][k] = 0.f;

    const uint32_t sw   = (uint32_t)(l & 7) << 4;
    const int rowA = wm + (l & 15);
    const uint32_t aColSel = ((uint32_t)(l >> 4)) << 4;
    const int rowB = wn + ((l >> 4) << 3) + (l & 7);
    const uint32_t bColSel = ((uint32_t)((l >> 3) & 1)) << 4;

    load_chunk(sb + 0 * STAGE_BYTES, 0, bm, bn, tid); CP_COMMIT();
    load_chunk(sb + 1 * STAGE_BYTES, 1, bm, bn, tid); CP_COMMIT();

    int rs = 0, ws = 2;
    for (int t = 0; t < KCHUNKS; t++) {
        CP_WAIT1();
        __syncthreads();

        if (t + 2 < KCHUNKS) load_chunk(sb + ws * STAGE_BYTES, t + 2, bm, bn, tid);
        CP_COMMIT();

        const uint32_t as = sb + rs * STAGE_BYTES;
        const uint32_t bs = as + TILE_BYTES;

        #pragma unroll
        for (int ks = 0; ks < 4; ks++) {
            const uint32_t kb = (uint32_t)ks * 32;
            uint32_t a[4][4], b[2][4];
            #pragma unroll
            for (int bt = 0; bt < 2; bt++)
                ldsm4(b[bt], bs + (uint32_t)(rowB + bt * 16) * 128 + ((kb + bColSel) ^ sw));
            #pragma unroll
            for (int mt = 0; mt < 4; mt++)
                ldsm4(a[mt], as + (uint32_t)(rowA + mt * 16) * 128 + ((kb + aColSel) ^ sw));
            #pragma unroll
            for (int mt = 0; mt < 4; mt++) {
                mma16816(acc[mt][0], a[mt], &b[0][0]);
                mma16816(acc[mt][1], a[mt], &b[0][2]);
                mma16816(acc[mt][2], a[mt], &b[1][0]);
                mma16816(acc[mt][3], a[mt], &b[1][2]);
            }
        }

        rs = (rs == 2) ? 0 : rs + 1;
        ws = (ws == 2) ? 0 : ws + 1;
    }

    // epilogue: coalesced stores at COMPACTED columns, guard c < V
    const int ccomp = bn + wn + (l & 3) * 2;
    const int rbase = bm + wm + (l >> 2);
    float m2v[4][2];
    bool  ok0[4], ok1[4];
    #pragma unroll
    for (int nt = 0; nt < 4; nt++) {
        const int c0 = ccomp + nt * 8;
        ok0[nt] = (c0 < V); ok1[nt] = (c0 + 1 < V);
        m2v[nt][0] = ok0[nt] ? g_m2c[c0]     : 0.f;
        m2v[nt][1] = ok1[nt] ? g_m2c[c0 + 1] : 0.f;
    }
    #pragma unroll
    for (int mt = 0; mt < 4; mt++) {
        const int r0 = rbase + mt * 16;
        const int r1 = r0 + 8;
        #pragma unroll
        for (int nt = 0; nt < 4; nt++) {
            const int c0 = ccomp + nt * 8;
            if (ok1[nt]) {
                float2 v0, v1;
                v0.x = 2.f * acc[mt][nt][0] - m2v[nt][0];
                v0.y = 2.f * acc[mt][nt][1] - m2v[nt][1];
                v1.x = 2.f * acc[mt][nt][2] - m2v[nt][0];
                v1.y = 2.f * acc[mt][nt][3] - m2v[nt][1];
                *(float2*)(S + (size_t)r0 * CCLS + c0) = v0;
                *(float2*)(S + (size_t)r1 * CCLS + c0) = v1;
            } else if (ok0[nt]) {
                S[(size_t)r0 * CCLS + c0] = 2.f * acc[mt][nt][0] - m2v[nt][0];
                S[(size_t)r1 * CCLS + c0] = 2.f * acc[mt][nt][2] - m2v[nt][0];
            }
        }
    }
}

// ===========================================================================
// Kernel: per-row softmax on compacted scores + gather-expand to full row.
// Unvisited classes output exactly 0 (reference underflows to 0 in fp32).
// ===========================================================================
__device__ __forceinline__ float block_red(float v, int mode, float* sred, int tid) {
    #pragma unroll
    for (int o = 16; o; o >>= 1) {
        float t = __shfl_xor_sync(0xffffffffu, v, o);
        v = (mode == 1) ? fmaxf(v, t) : (v + t);
    }
    __syncthreads();
    if ((tid & 31) == 0) sred[tid >> 5] = v;
    __syncthreads();
    float r;
    if (mode == 1) {
        r = fmaxf(fmaxf(fmaxf(sred[0], sred[1]), fmaxf(sred[2], sred[3])),
                  fmaxf(fmaxf(sred[4], sred[5]), fmaxf(sred[6], sred[7])));
    } else {
        r = ((sred[0] + sred[1]) + (sred[2] + sred[3])) +
            ((sred[4] + sred[5]) + (sred[6] + sred[7]));
    }
    return r;
}

__global__ __launch_bounds__(256) void k_softmax(float* __restrict__ S,
                                                 const float* __restrict__ cK) {
    __shared__ float sm_e[CCLS];
    __shared__ float sred[8];
    const int row = blockIdx.x;
    const int tid = threadIdx.x;
    const int V = g_V;
    float4* sp = (float4*)(S + (size_t)row * CCLS);

    // load compacted scores (coalesced); mask p >= V
    float4 v0 = sp[tid];
    float4 v1 = sp[tid + 256];
    const int p0 = tid * 4;
    const int p1 = 1024 + tid * 4;
    if (p0 + 0 >= V) v0.x = NEGHUGE;
    if (p0 + 1 >= V) v0.y = NEGHUGE;
    if (p0 + 2 >= V) v0.z = NEGHUGE;
    if (p0 + 3 >= V) v0.w = NEGHUGE;
    if (p1 + 0 >= V) v1.x = NEGHUGE;
    if (p1 + 1 >= V) v1.y = NEGHUGE;
    if (p1 + 2 >= V) v1.z = NEGHUGE;
    if (p1 + 3 >= V) v1.w = NEGHUGE;

    float mx = fmaxf(fmaxf(fmaxf(v0.x, v0.y), fmaxf(v0.z, v0.w)),
                     fmaxf(fmaxf(v1.x, v1.y), fmaxf(v1.z, v1.w)));
    mx = block_red(mx, 1, sred, tid);

    float4 e0, e1;
    e0.x = __expf(v0.x - mx); e0.y = __expf(v0.y - mx);
    e0.z = __expf(v0.z - mx); e0.w = __expf(v0.w - mx);
    e1.x = __expf(v1.x - mx); e1.y = __expf(v1.y - mx);
    e1.z = __expf(v1.z - mx); e1.w = __expf(v1.w - mx);
    float sum = ((e0.x + e0.y) + (e0.z + e0.w)) + ((e1.x + e1.y) + (e1.z + e1.w));
    sum = block_red(sum, 2, sred, tid);
    const float inv = 1.f / sum;

    // stage normalized probs in smem (compacted index space)
    ((float4*)sm_e)[tid]       = make_float4(e0.x * inv, e0.y * inv, e0.z * inv, e0.w * inv);
    ((float4*)sm_e)[tid + 256] = make_float4(e1.x * inv, e1.y * inv, e1.z * inv, e1.w * inv);
    __syncthreads();

    // gather-expand to full column space, coalesced float4 stores
    const float4* cp = (const float4*)cK;
    const int4*   qp = (const int4*)g_pos;
    float4 c0 = cp[tid], c1 = cp[tid + 256];
    int4   q0 = qp[tid], q1 = qp[tid + 256];
    float4 o0, o1;
    o0.x = (c0.x == 0.f) ? 0.f : sm_e[q0.x];
    o0.y = (c0.y == 0.f) ? 0.f : sm_e[q0.y];
    o0.z = (c0.z == 0.f) ? 0.f : sm_e[q0.z];
    o0.w = (c0.w == 0.f) ? 0.f : sm_e[q0.w];
    o1.x = (c1.x == 0.f) ? 0.f : sm_e[q1.x];
    o1.y = (c1.y == 0.f) ? 0.f : sm_e[q1.y];
    o1.z = (c1.z == 0.f) ? 0.f : sm_e[q1.z];
    o1.w = (c1.w == 0.f) ? 0.f : sm_e[q1.w];
    sp[tid]       = o0;
    sp[tid + 256] = o1;
}

// ===========================================================================
extern "C" void kernel_launch(void* const* d_in, const int* in_sizes, int n_in,
                              void* d_out, int out_size) {
    const float* X  = (const float*)d_in[0];   // (N, D) fp32
    const float* MU = (const float*)d_in[1];   // (C, D) fp32
    const float* cK = (const float*)d_in[2];   // (C,)   fp32
    float* out = (float*)d_out;                // (N, C) fp32

    cudaFuncSetAttribute(k_gemm_mma, cudaFuncAttributeMaxDynamicSharedMemorySize, SMEM_TOTAL);

    k_scan<<<1, 1024>>>(cK);
    k_convX<<<(NROWS * DDIM) / 4 / 256, 256>>>(X);
    k_convMU<<<CCLS, 128>>>(MU, cK);

    dim3 grid(CCLS / BN, NROWS / BM);          // (16, 256); pad tiles exit early
    k_gemm_mma<<<grid, 256, SMEM_TOTAL>>>(out);

    k_softmax<<<NROWS, 256>>>(out, cK);
}